// round 1
// baseline (speedup 1.0000x reference)
#include <cuda_runtime.h>
#include <cstdint>

// Problem constants
#define B_     2
#define N_IN_  163842
#define N_OUT_ 40962
#define C_     128
#define K_     7
#define C4_    (C_ / 4)   // 32 float4 per row
#define SIGMA_ 0.4f

// Scratch (allocation-free rule: __device__ globals)
__device__ __align__(16) float4 g_down[(size_t)B_ * N_OUT_ * C4_]; // 41.9 MB
__device__ float g_denom[N_OUT_];

// ---------------------------------------------------------------------------
// Zero the scratch buffers (d_out is poisoned; scratch must be zeroed per call)
// ---------------------------------------------------------------------------
__global__ void k_zero() {
    int tid = blockIdx.x * blockDim.x + threadIdx.x;
    const int nd = B_ * N_OUT_ * C4_;
    if (tid < nd) g_down[tid] = make_float4(0.f, 0.f, 0.f, 0.f);
    if (tid < N_OUT_) g_denom[tid] = 0.f;
}

// ---------------------------------------------------------------------------
// denom[p] += omega[n]  for parent p of n
// ---------------------------------------------------------------------------
__global__ void k_denom(const float* __restrict__ omega,
                        const int* __restrict__ parent) {
    int n = blockIdx.x * blockDim.x + threadIdx.x;
    if (n < N_IN_) atomicAdd(&g_denom[parent[n]], omega[n]);
}

// ---------------------------------------------------------------------------
// down[b, parent[n], :] += omega[n] * x[b, n, :]
// One warp-lane per float4 column chunk; vector RED keeps LTS op count at 1/4.
// grid = (ceil(N_IN/8), B), block = (32, 8)
// ---------------------------------------------------------------------------
__global__ void k_scatter(const float4* __restrict__ x,
                          const float* __restrict__ omega,
                          const int* __restrict__ parent) {
    int n = blockIdx.x * blockDim.y + threadIdx.y;
    if (n >= N_IN_) return;
    int b    = blockIdx.y;
    int lane = threadIdx.x;

    float om = __ldg(&omega[n]);           // broadcast within warp
    int   p  = __ldg(&parent[n]);
    float4 v = __ldg(&x[((size_t)b * N_IN_ + n) * C4_ + lane]);

    float4* dst = &g_down[((size_t)b * N_OUT_ + p) * C4_ + lane];
    asm volatile("red.global.add.v4.f32 [%0], {%1,%2,%3,%4};"
                 :: "l"(dst), "f"(v.x * om), "f"(v.y * om),
                    "f"(v.z * om), "f"(v.w * om)
                 : "memory");
}

// ---------------------------------------------------------------------------
// out[b,n,:] = sum_k ( w_nk / denom[cand_nk] ) * down[b, cand_nk, :]
// One warp per n, both batches inside -> 14 independent L2 gathers per lane.
// The down/denom normalization is folded into the weight (no normalize pass).
// grid = ceil(N_IN/8), block = (32, 8)
// ---------------------------------------------------------------------------
__global__ void k_gather(const float* __restrict__ delta,
                         const float* __restrict__ mask,
                         const int* __restrict__ cand,
                         float4* __restrict__ out) {
    int n = blockIdx.x * blockDim.y + threadIdx.y;
    if (n >= N_IN_) return;
    int lane = threadIdx.x;

    const float inv2s2 = 1.0f / (2.0f * SIGMA_ * SIGMA_);

    float e = 0.f, invden = 0.f;
    int   ci = 0;
    if (lane < K_) {
        float d = __ldg(&delta[n * K_ + lane]);
        float m = __ldg(&mask [n * K_ + lane]);
        e  = __expf(-d * d * inv2s2) * m;
        ci = __ldg(&cand[n * K_ + lane]);
        invden = 1.0f / fmaxf(g_denom[ci], 1e-8f);
    }

    // warp-sum of e (lanes >= K contribute 0)
    float s = e;
#pragma unroll
    for (int off = 16; off; off >>= 1)
        s += __shfl_xor_sync(0xffffffffu, s, off);

    float wp = e * invden / fmaxf(s, 1e-8f);

    float wk [K_];
    int   idx[K_];
#pragma unroll
    for (int k = 0; k < K_; k++) {
        wk [k] = __shfl_sync(0xffffffffu, wp, k);
        idx[k] = __shfl_sync(0xffffffffu, ci, k);
    }

#pragma unroll
    for (int b = 0; b < B_; b++) {
        float4 acc = make_float4(0.f, 0.f, 0.f, 0.f);
#pragma unroll
        for (int k = 0; k < K_; k++) {
            float4 v = __ldg(&g_down[((size_t)b * N_OUT_ + idx[k]) * C4_ + lane]);
            acc.x += wk[k] * v.x;
            acc.y += wk[k] * v.y;
            acc.z += wk[k] * v.z;
            acc.w += wk[k] * v.w;
        }
        out[((size_t)b * N_IN_ + n) * C4_ + lane] = acc;
    }
}

// ---------------------------------------------------------------------------
// Harness entry. Input order per metadata: x, omega, delta, cand_mask,
// parent_idx, cand_idx. Output: float32, (B, N_IN, C).
// ---------------------------------------------------------------------------
extern "C" void kernel_launch(void* const* d_in, const int* in_sizes, int n_in,
                              void* d_out, int out_size) {
    const float4* x      = (const float4*)d_in[0];
    const float*  omega  = (const float*) d_in[1];
    const float*  delta  = (const float*) d_in[2];
    const float*  cmask  = (const float*) d_in[3];
    const int*    parent = (const int*)   d_in[4];
    const int*    cand   = (const int*)   d_in[5];
    float4*       out    = (float4*)      d_out;

    const int nd = B_ * N_OUT_ * C4_;
    k_zero<<<(nd + 255) / 256, 256>>>();

    k_denom<<<(N_IN_ + 255) / 256, 256>>>(omega, parent);

    dim3 bs(32, 8);
    int nb = (N_IN_ + 7) / 8;
    k_scatter<<<dim3(nb, B_), bs>>>(x, omega, parent);

    k_gather<<<nb, bs>>>(delta, cmask, cand, out);
}

// round 2
// speedup vs baseline: 1.0939x; 1.0939x over previous
#include <cuda_runtime.h>
#include <cuda_fp16.h>
#include <cstdint>

// Problem constants
#define B_     2
#define N_IN_  163842
#define N_OUT_ 40962
#define C_     128
#define K_     7
#define C4_    (C_ / 4)    // 32 float4 per fp32 row
#define H2_    (C_ / 2)    // 64 half2 per fp16 row
#define SIGMA_ 0.4f

// Scratch (allocation-free rule: __device__ globals)
__device__ __align__(16) float4  g_down [(size_t)B_ * N_OUT_ * C4_]; // 41.9 MB fp32 accumulator
__device__ __align__(16) __half2 g_downh[(size_t)B_ * N_OUT_ * H2_]; // 21.0 MB fp16 gather source
__device__ float g_denom[N_OUT_];

// ---------------------------------------------------------------------------
// Zero fp32 accumulator + denom (fp16 buffer is fully overwritten by convert)
// ---------------------------------------------------------------------------
__global__ void k_zero() {
    int tid = blockIdx.x * blockDim.x + threadIdx.x;
    const int nd = B_ * N_OUT_ * C4_;
    if (tid < nd) g_down[tid] = make_float4(0.f, 0.f, 0.f, 0.f);
    if (tid < N_OUT_) g_denom[tid] = 0.f;
}

// ---------------------------------------------------------------------------
// down[b, parent[n], :] += omega[n] * x[b, n, :]   (+ denom scatter, b==0)
// grid = (ceil(N_IN/8), B), block = (32, 8)
// ---------------------------------------------------------------------------
__global__ void k_scatter(const float4* __restrict__ x,
                          const float* __restrict__ omega,
                          const int* __restrict__ parent) {
    int n = blockIdx.x * blockDim.y + threadIdx.y;
    if (n >= N_IN_) return;
    int b    = blockIdx.y;
    int lane = threadIdx.x;

    float om = __ldg(&omega[n]);           // broadcast within warp
    int   p  = __ldg(&parent[n]);

    if (b == 0 && lane == 0) atomicAdd(&g_denom[p], om);

    float4 v = __ldg(&x[((size_t)b * N_IN_ + n) * C4_ + lane]);
    float4* dst = &g_down[((size_t)b * N_OUT_ + p) * C4_ + lane];
    asm volatile("red.global.add.v4.f32 [%0], {%1,%2,%3,%4};"
                 :: "l"(dst), "f"(v.x * om), "f"(v.y * om),
                    "f"(v.z * om), "f"(v.w * om)
                 : "memory");
}

// ---------------------------------------------------------------------------
// fp32 accumulator -> fp16 gather source (L2-resident, ~63 MB total traffic)
// ---------------------------------------------------------------------------
__global__ void k_convert() {
    int tid = blockIdx.x * blockDim.x + threadIdx.x;
    const int nd = B_ * N_OUT_ * C4_;
    if (tid >= nd) return;
    float4 v = g_down[tid];
    g_downh[2 * tid + 0] = __floats2half2_rn(v.x, v.y);
    g_downh[2 * tid + 1] = __floats2half2_rn(v.z, v.w);
}

// ---------------------------------------------------------------------------
// out[b,n,:] = sum_k ( w_nk / denom[cand_nk] ) * down_h[b, cand_nk, :]
// One warp per n, both batches. Each lane owns 4 channels:
//   load = 8 B (uint2 = 2 half2) -> 2 L1 wavefronts per row vs 4 for fp32.
// grid = ceil(N_IN/8), block = (32, 8)
// ---------------------------------------------------------------------------
__global__ void __launch_bounds__(256, 6)
k_gather(const float* __restrict__ delta,
         const float* __restrict__ mask,
         const int* __restrict__ cand,
         float4* __restrict__ out) {
    int n = blockIdx.x * blockDim.y + threadIdx.y;
    if (n >= N_IN_) return;
    int lane = threadIdx.x;

    const float inv2s2 = 1.0f / (2.0f * SIGMA_ * SIGMA_);

    float e = 0.f, invden = 0.f;
    int   ci = 0;
    if (lane < K_) {
        float d = __ldg(&delta[n * K_ + lane]);
        float m = __ldg(&mask [n * K_ + lane]);
        e  = __expf(-d * d * inv2s2) * m;
        ci = __ldg(&cand[n * K_ + lane]);
        invden = 1.0f / fmaxf(g_denom[ci], 1e-8f);
    }

    // warp-sum of e (lanes >= K contribute 0)
    float s = e;
#pragma unroll
    for (int off = 16; off; off >>= 1)
        s += __shfl_xor_sync(0xffffffffu, s, off);

    float wp = e * invden / fmaxf(s, 1e-8f);

    float wk [K_];
    int   idx[K_];
#pragma unroll
    for (int k = 0; k < K_; k++) {
        wk [k] = __shfl_sync(0xffffffffu, wp, k);
        idx[k] = __shfl_sync(0xffffffffu, ci, k);
    }

#pragma unroll
    for (int b = 0; b < B_; b++) {
        // issue all 7 independent 8-byte loads first (MLP)
        uint2 raw[K_];
#pragma unroll
        for (int k = 0; k < K_; k++) {
            const uint2* src = (const uint2*)
                &g_downh[((size_t)b * N_OUT_ + idx[k]) * H2_ + 2 * lane];
            raw[k] = __ldg(src);
        }
        float4 acc = make_float4(0.f, 0.f, 0.f, 0.f);
#pragma unroll
        for (int k = 0; k < K_; k++) {
            float2 lo = __half22float2(*(const __half2*)&raw[k].x);
            float2 hi = __half22float2(*(const __half2*)&raw[k].y);
            acc.x = fmaf(wk[k], lo.x, acc.x);
            acc.y = fmaf(wk[k], lo.y, acc.y);
            acc.z = fmaf(wk[k], hi.x, acc.z);
            acc.w = fmaf(wk[k], hi.y, acc.w);
        }
        out[((size_t)b * N_IN_ + n) * C4_ + lane] = acc;
    }
}

// ---------------------------------------------------------------------------
// Harness entry. Inputs: x, omega, delta, cand_mask, parent_idx, cand_idx.
// Output: float32, (B, N_IN, C).
// ---------------------------------------------------------------------------
extern "C" void kernel_launch(void* const* d_in, const int* in_sizes, int n_in,
                              void* d_out, int out_size) {
    const float4* x      = (const float4*)d_in[0];
    const float*  omega  = (const float*) d_in[1];
    const float*  delta  = (const float*) d_in[2];
    const float*  cmask  = (const float*) d_in[3];
    const int*    parent = (const int*)   d_in[4];
    const int*    cand   = (const int*)   d_in[5];
    float4*       out    = (float4*)      d_out;

    const int nd = B_ * N_OUT_ * C4_;
    k_zero<<<(nd + 255) / 256, 256>>>();

    dim3 bs(32, 8);
    int nb = (N_IN_ + 7) / 8;
    k_scatter<<<dim3(nb, B_), bs>>>(x, omega, parent);

    k_convert<<<(nd + 255) / 256, 256>>>();

    k_gather<<<nb, bs>>>(delta, cmask, cand, out);
}